// round 15
// baseline (speedup 1.0000x reference)
#include <cuda_runtime.h>
#include <cuda_bf16.h>
#include <cuda_fp16.h>
#include <cstdint>

#define BSZ   4096
#define DIM   1024
#define NC    100
#define NCP   128
#define NITER 30
#define NLAB  2048
#define GT    32
#define NTRI  (GT * (GT + 1) / 2)
#define NSPL  8

// ---- scratch (static device globals) ----
__device__ __nv_bfloat16 g_neh[(size_t)BSZ * DIM];
__device__ __nv_bfloat16 g_nel[(size_t)BSZ * DIM];
__device__ float g_A[(size_t)BSZ * BSZ];
__device__ __half g_Af16[(size_t)BSZ * BSZ];
__device__ float g_Xf[2][(size_t)BSZ * NCP];
__device__ __half g_Xt16[2][(size_t)NCP * BSZ];
__device__ float g_D[NSPL][(size_t)BSZ * NCP];
__device__ float g_sXs[(size_t)NITER * BSZ * NC];   // staged dv, [t][b][cc]
__device__ float g_sEnt[(size_t)NITER * BSZ];       // staged entropy, [t][b]
__device__ float g_part[1024];
__device__ float g_mean;

// ==================== asm helpers (base PTX) ====================
__device__ __forceinline__ uint32_t smem_u32(const void* p) {
    uint32_t a;
    asm("{ .reg .u64 t; cvta.to.shared.u64 t, %1; cvt.u32.u64 %0, t; }" : "=r"(a) : "l"(p));
    return a;
}
__device__ __forceinline__ void cp16(uint32_t dst, const void* src) {
    asm volatile("cp.async.cg.shared.global [%0], [%1], 16;"
                 :: "r"(dst), "l"(__cvta_generic_to_global(src)) : "memory");
}
__device__ __forceinline__ void cp_commit() {
    asm volatile("cp.async.commit_group;" ::: "memory");
}
template <int N>
__device__ __forceinline__ void cp_wait() {
    asm volatile("cp.async.wait_group %0;" :: "n"(N) : "memory");
}
__device__ __forceinline__ void ldmx4(uint32_t* r, uint32_t addr) {
    asm volatile("ldmatrix.sync.aligned.m8n8.x4.shared.b16 {%0,%1,%2,%3}, [%4];"
                 : "=r"(r[0]), "=r"(r[1]), "=r"(r[2]), "=r"(r[3]) : "r"(addr));
}
__device__ __forceinline__ void mma16816_bf(float* d, const uint32_t* a, const uint32_t* b) {
    asm volatile("mma.sync.aligned.m16n8k16.row.col.f32.bf16.bf16.f32 "
                 "{%0,%1,%2,%3}, {%4,%5,%6,%7}, {%8,%9}, {%0,%1,%2,%3};"
                 : "+f"(d[0]), "+f"(d[1]), "+f"(d[2]), "+f"(d[3])
                 : "r"(a[0]), "r"(a[1]), "r"(a[2]), "r"(a[3]), "r"(b[0]), "r"(b[1]));
}
__device__ __forceinline__ void mma16816_hf(float* d, const uint32_t* a, const uint32_t* b) {
    asm volatile("mma.sync.aligned.m16n8k16.row.col.f32.f16.f16.f32 "
                 "{%0,%1,%2,%3}, {%4,%5,%6,%7}, {%8,%9}, {%0,%1,%2,%3};"
                 : "+f"(d[0]), "+f"(d[1]), "+f"(d[2]), "+f"(d[3])
                 : "r"(a[0]), "r"(a[1]), "r"(a[2]), "r"(a[3]), "r"(b[0]), "r"(b[1]));
}
__device__ __forceinline__ uint32_t swz(uint32_t row, uint32_t gran16) {
    return (row * 128u + gran16 * 16u) ^ ((row & 7u) << 4);
}

// ==================== K1: row-normalize -> bf16 hi/lo ====================
__global__ void k_normalize(const float* __restrict__ emb) {
    int r = blockIdx.x;
    int tid = threadIdx.x;
    float4 x = ((const float4*)(emb + (size_t)r * DIM))[tid];
    float ss = x.x * x.x + x.y * x.y + x.z * x.z + x.w * x.w;
    __shared__ float red[8];
#pragma unroll
    for (int o = 16; o; o >>= 1) ss += __shfl_xor_sync(0xffffffffu, ss, o);
    if ((tid & 31) == 0) red[tid >> 5] = ss;
    __syncthreads();
    float tot = red[0] + red[1] + red[2] + red[3] + red[4] + red[5] + red[6] + red[7];
    float sc = 1.f / (sqrtf(tot) + 1e-12f);
    float v[4] = {x.x * sc, x.y * sc, x.z * sc, x.w * sc};
    uint32_t hh[2], ll[2];
#pragma unroll
    for (int j = 0; j < 2; j++) {
        __nv_bfloat16 h0 = __float2bfloat16(v[2 * j]);
        __nv_bfloat16 h1 = __float2bfloat16(v[2 * j + 1]);
        __nv_bfloat16 l0 = __float2bfloat16(v[2 * j] - __bfloat162float(h0));
        __nv_bfloat16 l1 = __float2bfloat16(v[2 * j + 1] - __bfloat162float(h1));
        hh[j] = (uint32_t)__bfloat16_as_ushort(h0) | ((uint32_t)__bfloat16_as_ushort(h1) << 16);
        ll[j] = (uint32_t)__bfloat16_as_ushort(l0) | ((uint32_t)__bfloat16_as_ushort(l1) << 16);
    }
    ((uint2*)(g_neh + (size_t)r * DIM))[tid] = make_uint2(hh[0], hh[1]);
    ((uint2*)(g_nel + (size_t)r * DIM))[tid] = make_uint2(ll[0], ll[1]);
}

// ==================== K2: A = clamp(ne @ ne^T), HMMA split-3, single-buffer, 2 CTA/SM ====================
#define AKC 64
#define ACH (DIM / AKC)
#define A_AH 0
#define A_AL 16384
#define A_BH 32768
#define A_BL 49152
#define A_DSMEM (1024 + 128 * 130 * 4)

__global__ void __launch_bounds__(256, 2) k_gemmA_mma() {
    extern __shared__ char dsm[];
    __shared__ float sred[8];
    uint32_t raw = smem_u32(dsm);
    uint32_t sbase = ((raw + 1023u) & ~1023u);
    char* sgen = dsm + (sbase - raw);
    uint32_t stg = sbase;

    int tid = threadIdx.x, wid = tid >> 5, lane = tid & 31;
    int wm = wid >> 2, wn = wid & 3;

    int b = blockIdx.x;
    int ti = 0;
    while ((ti + 1) * GT - ti * (ti + 1) / 2 <= b) ti++;
    int tj = ti + (b - (ti * GT - ti * (ti - 1) / 2));
    int r0 = ti * 128, c0 = tj * 128;

    auto load_stage = [&](int k0) {
        int g = tid & 7, rb = tid >> 3;
#pragma unroll
        for (int j = 0; j < 4; j++) {
            int row = rb + 32 * j;
            size_t ga = (size_t)(r0 + row) * DIM + k0 + g * 8;
            size_t gb = (size_t)(c0 + row) * DIM + k0 + g * 8;
            uint32_t so = swz(row, g);
            cp16(stg + A_AH + so, g_neh + ga);
            cp16(stg + A_AL + so, g_nel + ga);
            cp16(stg + A_BH + so, g_neh + gb);
            cp16(stg + A_BL + so, g_nel + gb);
        }
        cp_commit();
    };

    float acc[4][4][4];
#pragma unroll
    for (int q = 0; q < 4; q++)
#pragma unroll
        for (int nt = 0; nt < 4; nt++)
#pragma unroll
            for (int e = 0; e < 4; e++) acc[q][nt][e] = 0.f;

    load_stage(0);

    for (int c = 0; c < ACH; c++) {
        cp_wait<0>();
        __syncthreads();
#pragma unroll
        for (int ks = 0; ks < 4; ks++) {
            uint32_t ah[4][4], al[4][4];
#pragma unroll
            for (int q = 0; q < 4; q++) {
                uint32_t off = swz(wm * 64 + q * 16 + (lane & 15), ks * 2 + (lane >> 4));
                ldmx4(ah[q], stg + A_AH + off);
                ldmx4(al[q], stg + A_AL + off);
            }
            uint32_t bh[4][2], bl[4][2];
#pragma unroll
            for (int p = 0; p < 2; p++) {
                uint32_t row = wn * 32 + p * 16 + (lane & 7) + ((lane >> 4) & 1) * 8;
                uint32_t off = swz(row, ks * 2 + ((lane >> 3) & 1));
                uint32_t t4[4];
                ldmx4(t4, stg + A_BH + off);
                bh[2 * p][0] = t4[0]; bh[2 * p][1] = t4[1];
                bh[2 * p + 1][0] = t4[2]; bh[2 * p + 1][1] = t4[3];
                ldmx4(t4, stg + A_BL + off);
                bl[2 * p][0] = t4[0]; bl[2 * p][1] = t4[1];
                bl[2 * p + 1][0] = t4[2]; bl[2 * p + 1][1] = t4[3];
            }
#pragma unroll
            for (int q = 0; q < 4; q++)
#pragma unroll
                for (int nt = 0; nt < 4; nt++) {
                    mma16816_bf(acc[q][nt], ah[q], bh[nt]);
                    mma16816_bf(acc[q][nt], ah[q], bl[nt]);
                    mma16816_bf(acc[q][nt], al[q], bh[nt]);
                }
        }
        __syncthreads();
        if (c + 1 < ACH) load_stage((c + 1) * AKC);
    }

    float* Cs = (float*)sgen;
#pragma unroll
    for (int q = 0; q < 4; q++) {
        int row = wm * 64 + q * 16 + (lane >> 2);
        int col = wn * 32 + (lane & 3) * 2;
#pragma unroll
        for (int nt = 0; nt < 4; nt++) {
            Cs[row * 130 + col + nt * 8]           = acc[q][nt][0];
            Cs[row * 130 + col + nt * 8 + 1]       = acc[q][nt][1];
            Cs[(row + 8) * 130 + col + nt * 8]     = acc[q][nt][2];
            Cs[(row + 8) * 130 + col + nt * 8 + 1] = acc[q][nt][3];
        }
    }
    __syncthreads();
    float s = 0.f;
    for (int idx = tid; idx < 128 * 128; idx += 256) {
        int i = idx >> 7, j = idx & 127;
        int gi = r0 + i, gj = c0 + j;
        float v = Cs[i * 130 + j];
        v = (gi == gj) ? 0.f : fminf(fmaxf(v, 0.f), 1.f);
        s += v;
        g_A[(size_t)gi * BSZ + gj] = v;
    }
    if (ti != tj) {
        for (int idx = tid; idx < 128 * 128; idx += 256) {
            int i = idx >> 7, j = idx & 127;
            float v = Cs[j * 130 + i];
            v = fminf(fmaxf(v, 0.f), 1.f);
            g_A[(size_t)(c0 + i) * BSZ + (r0 + j)] = v;
        }
    }
#pragma unroll
    for (int o = 16; o; o >>= 1) s += __shfl_xor_sync(0xffffffffu, s, o);
    if (lane == 0) sred[wid] = s;
    __syncthreads();
    if (tid == 0) {
        float t = 0.f;
#pragma unroll
        for (int i = 0; i < 8; i++) t += sred[i];
        g_part[b] = t * ((ti == tj) ? 1.f : 2.f);
    }
}

// ==================== K3: final mean reduce ====================
__global__ void k_mean2() {
    __shared__ float red[1024];
    int tid = threadIdx.x;
    red[tid] = (tid < NTRI) ? g_part[tid] : 0.f;
    __syncthreads();
    for (int o = 512; o; o >>= 1) {
        if (tid < o) red[tid] += red[tid + o];
        __syncthreads();
    }
    if (tid == 0) g_mean = red[0] * (1.f / ((float)BSZ * (float)BSZ));
}

// ==================== K5: threshold + fp16 cast of A ====================
__global__ void k_splitA() {
    float m = g_mean;
    size_t i = ((size_t)blockIdx.x * 256 + threadIdx.x) * 8;
    float4 v0 = *(const float4*)(g_A + i);
    float4 v1 = *(const float4*)(g_A + i + 4);
    float f[8] = {v0.x, v0.y, v0.z, v0.w, v1.x, v1.y, v1.z, v1.w};
    uint32_t hw[4];
#pragma unroll
    for (int j = 0; j < 4; j++) {
        float f0 = (f[2 * j]     < m) ? 0.f : f[2 * j];
        float f1 = (f[2 * j + 1] < m) ? 0.f : f[2 * j + 1];
        __half h0 = __float2half_rn(f0), h1 = __float2half_rn(f1);
        hw[j] = (uint32_t)__half_as_ushort(h0) | ((uint32_t)__half_as_ushort(h1) << 16);
    }
    *(uint4*)(g_Af16 + i) = make_uint4(hw[0], hw[1], hw[2], hw[3]);
}

// ==================== K6: init X ====================
__global__ void k_initX(const int* __restrict__ labels) {
    int r = blockIdx.x, c = threadIdx.x;
    float v;
    if (r < NLAB) v = (c == labels[r]) ? 1.f : 0.f;
    else          v = (c < NC) ? 0.01f : 0.f;
    g_Xf[0][(size_t)r * NCP + c] = v;
    g_Xt16[0][(size_t)c * BSZ + r] = __float2half_rn(v);
}

// ==================== K7: iteration GEMM (M-tile 256, warp 64x64, K-split x8) ====================
#define I_A 0
#define I_X 32768
#define I_STAGE 49152
#define I_NSTG 3
#define I_DSMEM (1024 + I_NSTG * I_STAGE)   // 148.5 KB -> 1 CTA/SM

__global__ void __launch_bounds__(256, 1) k_iter_gemm(int t) {
    extern __shared__ char dsm[];
    uint32_t raw = smem_u32(dsm);
    uint32_t sbase = ((raw + 1023u) & ~1023u);
    uint32_t stg = sbase;

    int tid = threadIdx.x, wid = tid >> 5, lane = tid & 31;
    int wm = wid >> 1, wn = wid & 1;              // warp tile 64m x 64n
    int ks = blockIdx.x >> 4, mt = blockIdx.x & 15;
    int r0 = mt * 256;
    int kb = ks * (BSZ / NSPL);

    const __half* __restrict__ Af = g_Af16;
    const __half* __restrict__ Xt = g_Xt16[t & 1];

    auto load_stage = [&](int k0, int buf) {
        uint32_t bu = stg + buf * I_STAGE;
        int g = tid & 7, rb = tid >> 3;           // rb 0..31
#pragma unroll
        for (int j = 0; j < 8; j++) {             // A: 256 rows
            int row = rb + 32 * j;
            size_t ga = (size_t)(r0 + row) * BSZ + kb + k0 + g * 8;
            cp16(bu + I_A + swz(row, g), Af + ga);
        }
#pragma unroll
        for (int j = 0; j < 4; j++) {             // X: 128 rows
            int row = rb + 32 * j;
            size_t gx = (size_t)row * BSZ + kb + k0 + g * 8;
            cp16(bu + I_X + swz(row, g), Xt + gx);
        }
        cp_commit();
    };

    float acc[4][8][4];
#pragma unroll
    for (int q = 0; q < 4; q++)
#pragma unroll
        for (int nt = 0; nt < 8; nt++)
#pragma unroll
            for (int e = 0; e < 4; e++) acc[q][nt][e] = 0.f;

    const int KCH = (BSZ / NSPL) / AKC;           // 8 chunks
    load_stage(0, 0);
    load_stage(AKC, 1);
    load_stage(2 * AKC, 2);

    for (int c = 0; c < KCH; c++) {
        if (c >= KCH - 1)      cp_wait<0>();
        else if (c == KCH - 2) cp_wait<1>();
        else                   cp_wait<2>();
        __syncthreads();
        uint32_t bu = stg + (c % I_NSTG) * I_STAGE;
#pragma unroll
        for (int kq = 0; kq < 4; kq++) {
            uint32_t a[4][4];
#pragma unroll
            for (int q = 0; q < 4; q++) {
                uint32_t off = swz(wm * 64 + q * 16 + (lane & 15), kq * 2 + (lane >> 4));
                ldmx4(a[q], bu + I_A + off);
            }
            uint32_t bm[8][2];
#pragma unroll
            for (int p = 0; p < 4; p++) {
                uint32_t row = wn * 64 + p * 16 + (lane & 7) + ((lane >> 4) & 1) * 8;
                uint32_t off = swz(row, kq * 2 + ((lane >> 3) & 1));
                uint32_t t4[4];
                ldmx4(t4, bu + I_X + off);
                bm[2 * p][0] = t4[0]; bm[2 * p][1] = t4[1];
                bm[2 * p + 1][0] = t4[2]; bm[2 * p + 1][1] = t4[3];
            }
#pragma unroll
            for (int q = 0; q < 4; q++)
#pragma unroll
                for (int nt = 0; nt < 8; nt++)
                    mma16816_hf(acc[q][nt], a[q], bm[nt]);
        }
        __syncthreads();
        if (c + 3 < KCH) load_stage((c + 3) * AKC, (c + 3) % I_NSTG);
    }

    float* P = g_D[ks];
#pragma unroll
    for (int q = 0; q < 4; q++) {
        int row = wm * 64 + q * 16 + (lane >> 2);
        int col = wn * 64 + 2 * (lane & 3);
#pragma unroll
        for (int nt = 0; nt < 8; nt++) {
            *(float2*)(P + (size_t)(r0 + row) * NCP + col + nt * 8) =
                make_float2(acc[q][nt][0], acc[q][nt][1]);
            *(float2*)(P + (size_t)(r0 + row + 8) * NCP + col + nt * 8) =
                make_float2(acc[q][nt][2], acc[q][nt][3]);
        }
    }
}

// ==================== K8: epilogue (sum partials, div/entropy, staged outputs) ====================
__global__ void __launch_bounds__(256) k_epi(int t) {
    __shared__ __half sp16[NCP * 32];
    int tid = threadIdx.x;
    int row = tid >> 3, part = tid & 7;
    int r0 = blockIdx.x * 32;
    int gr = r0 + row;
    const float* __restrict__ Xin = g_Xf[t & 1];
    float* __restrict__ Xout = g_Xf[(t + 1) & 1];
    float* __restrict__ sXs  = g_sXs + (size_t)t * BSZ * NC;
    float* __restrict__ sEnt = g_sEnt + (size_t)t * BSZ;

    float dd[16], xv[16], num[16];
    float s = 0.f;
    size_t base = (size_t)gr * NCP + part * 16;
#pragma unroll
    for (int v = 0; v < 4; v++) {
        size_t off = base + v * 4;
        float4 acc4 = *(const float4*)(g_D[0] + off);
#pragma unroll
        for (int p = 1; p < NSPL; p++) {
            float4 pp = *(const float4*)(g_D[p] + off);
            acc4.x += pp.x; acc4.y += pp.y; acc4.z += pp.z; acc4.w += pp.w;
        }
        dd[v * 4 + 0] = acc4.x; dd[v * 4 + 1] = acc4.y;
        dd[v * 4 + 2] = acc4.z; dd[v * 4 + 3] = acc4.w;
        float4 x4 = *(const float4*)(Xin + off);
        xv[v * 4 + 0] = x4.x; xv[v * 4 + 1] = x4.y;
        xv[v * 4 + 2] = x4.z; xv[v * 4 + 3] = x4.w;
    }
#pragma unroll
    for (int i = 0; i < 16; i++) {
        int cc = part * 16 + i;
        num[i] = (cc < NC) ? xv[i] * dd[i] : 0.f;
        s += num[i];
    }
    s += __shfl_xor_sync(0xffffffffu, s, 1);
    s += __shfl_xor_sync(0xffffffffu, s, 2);
    s += __shfl_xor_sync(0xffffffffu, s, 4);
    float inv = 1.f / (s + 1e-8f);

    float ep = 0.f;
#pragma unroll
    for (int v = 0; v < 4; v++) {
        float xo4[4];
#pragma unroll
        for (int i = 0; i < 4; i++) {
            int idx = v * 4 + i;
            int cc = part * 16 + idx;
            float dv = num[idx] * inv;
            float xo = xv[idx] + dv;
            if (cc < NC) {
                ep += dv * __logf(dv + 1e-20f);
                sXs[(size_t)gr * NC + cc] = dv;
            }
            xo4[i] = xo;
            sp16[cc * 32 + row] = __float2half_rn(xo);
        }
        *(float4*)(Xout + base + v * 4) = make_float4(xo4[0], xo4[1], xo4[2], xo4[3]);
    }
    ep += __shfl_xor_sync(0xffffffffu, ep, 1);
    ep += __shfl_xor_sync(0xffffffffu, ep, 2);
    ep += __shfl_xor_sync(0xffffffffu, ep, 4);
    if (part == 0) sEnt[gr] = -ep;
    __syncthreads();

    __half* XtN = g_Xt16[(t + 1) & 1];
    for (int idx = tid; idx < NCP * 16; idx += 256) {
        int cc = idx >> 4;
        int pos = (idx & 15) * 2;
        uint32_t h0 = (uint32_t)__half_as_ushort(sp16[cc * 32 + pos]);
        uint32_t h1 = (uint32_t)__half_as_ushort(sp16[cc * 32 + pos + 1]);
        *(uint32_t*)(XtN + (size_t)cc * BSZ + r0 + pos) = h0 | (h1 << 16);
    }
}

// ==================== K9: finalize outputs ====================
__global__ void __launch_bounds__(256) k_finalize(float* __restrict__ outXs,
                                                  float* __restrict__ outEnt) {
    __shared__ float s[NC * NITER];
    int b = blockIdx.x, tid = threadIdx.x;
    for (int i = tid; i < NITER * NC; i += 256) {
        int t = i / NC, cc = i - t * NC;
        s[cc * NITER + t] = g_sXs[((size_t)t * BSZ + b) * NC + cc];
    }
    __syncthreads();
    for (int i = tid; i < NC * NITER; i += 256)
        outXs[(size_t)b * (NC * NITER) + i] = s[i];
    if (tid < NITER)
        outEnt[(size_t)b * NITER + tid] = g_sEnt[(size_t)tid * BSZ + b];
}

// ==================== launch ====================
extern "C" void kernel_launch(void* const* d_in, const int* in_sizes, int n_in,
                              void* d_out, int out_size) {
    (void)in_sizes; (void)n_in; (void)out_size;
    const float* emb = (const float*)d_in[0];
    const int* labels = (const int*)d_in[1];
    float* out = (float*)d_out;
    float* outXs = out;
    float* outEnt = out + (size_t)BSZ * NC * NITER;

    cudaFuncSetAttribute(k_gemmA_mma, cudaFuncAttributeMaxDynamicSharedMemorySize, A_DSMEM);
    cudaFuncSetAttribute(k_iter_gemm, cudaFuncAttributeMaxDynamicSharedMemorySize, I_DSMEM);

    k_normalize<<<BSZ, 256>>>(emb);
    k_gemmA_mma<<<NTRI, 256, A_DSMEM>>>();
    k_mean2<<<1, 1024>>>();
    k_splitA<<<(int)(((size_t)BSZ * BSZ) / (8 * 256)), 256>>>();
    k_initX<<<BSZ, NCP>>>(labels);
    for (int t = 0; t < NITER; t++) {
        k_iter_gemm<<<NSPL * 16, 256, I_DSMEM>>>(t);
        k_epi<<<BSZ / 32, 256>>>(t);
    }
    k_finalize<<<BSZ, 256>>>(outXs, outEnt);
}

// round 16
// speedup vs baseline: 1.0321x; 1.0321x over previous
#include <cuda_runtime.h>
#include <cuda_bf16.h>
#include <cuda_fp16.h>
#include <cstdint>

#define BSZ   4096
#define DIM   1024
#define NC    100
#define NCP   128
#define NITER 30
#define NLAB  2048
#define GT    32
#define NTRI  (GT * (GT + 1) / 2)
#define NSPL  4

// ---- scratch (static device globals) ----
__device__ __nv_bfloat16 g_neh[(size_t)BSZ * DIM];
__device__ __nv_bfloat16 g_nel[(size_t)BSZ * DIM];
__device__ float g_A[(size_t)BSZ * BSZ];
__device__ __half g_Af16[(size_t)BSZ * BSZ];
__device__ float g_Xf[2][(size_t)BSZ * NCP];
__device__ __half g_Xt16[2][(size_t)NCP * BSZ];
__device__ float g_D[NSPL][(size_t)BSZ * NCP];
__device__ float g_sXs[(size_t)NITER * BSZ * NC];   // staged dv, [t][b][cc]
__device__ float g_sEnt[(size_t)NITER * BSZ];       // staged entropy, [t][b]
__device__ float g_part[1024];                      // 528 tile sums (rest zero)
__device__ float g_mean;

// ==================== asm helpers (base PTX) ====================
__device__ __forceinline__ uint32_t smem_u32(const void* p) {
    uint32_t a;
    asm("{ .reg .u64 t; cvta.to.shared.u64 t, %1; cvt.u32.u64 %0, t; }" : "=r"(a) : "l"(p));
    return a;
}
__device__ __forceinline__ void cp16(uint32_t dst, const void* src) {
    asm volatile("cp.async.cg.shared.global [%0], [%1], 16;"
                 :: "r"(dst), "l"(__cvta_generic_to_global(src)) : "memory");
}
__device__ __forceinline__ void cp_commit() {
    asm volatile("cp.async.commit_group;" ::: "memory");
}
template <int N>
__device__ __forceinline__ void cp_wait() {
    asm volatile("cp.async.wait_group %0;" :: "n"(N) : "memory");
}
__device__ __forceinline__ void ldmx4(uint32_t* r, uint32_t addr) {
    asm volatile("ldmatrix.sync.aligned.m8n8.x4.shared.b16 {%0,%1,%2,%3}, [%4];"
                 : "=r"(r[0]), "=r"(r[1]), "=r"(r[2]), "=r"(r[3]) : "r"(addr));
}
__device__ __forceinline__ void mma16816_bf(float* d, const uint32_t* a, const uint32_t* b) {
    asm volatile("mma.sync.aligned.m16n8k16.row.col.f32.bf16.bf16.f32 "
                 "{%0,%1,%2,%3}, {%4,%5,%6,%7}, {%8,%9}, {%0,%1,%2,%3};"
                 : "+f"(d[0]), "+f"(d[1]), "+f"(d[2]), "+f"(d[3])
                 : "r"(a[0]), "r"(a[1]), "r"(a[2]), "r"(a[3]), "r"(b[0]), "r"(b[1]));
}
__device__ __forceinline__ void mma16816_hf(float* d, const uint32_t* a, const uint32_t* b) {
    asm volatile("mma.sync.aligned.m16n8k16.row.col.f32.f16.f16.f32 "
                 "{%0,%1,%2,%3}, {%4,%5,%6,%7}, {%8,%9}, {%0,%1,%2,%3};"
                 : "+f"(d[0]), "+f"(d[1]), "+f"(d[2]), "+f"(d[3])
                 : "r"(a[0]), "r"(a[1]), "r"(a[2]), "r"(a[3]), "r"(b[0]), "r"(b[1]));
}
__device__ __forceinline__ uint32_t swz(uint32_t row, uint32_t gran16) {
    return (row * 128u + gran16 * 16u) ^ ((row & 7u) << 4);
}

// ==================== K1: row-normalize -> bf16 hi/lo ====================
__global__ void k_normalize(const float* __restrict__ emb) {
    int r = blockIdx.x;
    int tid = threadIdx.x;
    float4 x = ((const float4*)(emb + (size_t)r * DIM))[tid];
    float ss = x.x * x.x + x.y * x.y + x.z * x.z + x.w * x.w;
    __shared__ float red[8];
#pragma unroll
    for (int o = 16; o; o >>= 1) ss += __shfl_xor_sync(0xffffffffu, ss, o);
    if ((tid & 31) == 0) red[tid >> 5] = ss;
    __syncthreads();
    float tot = red[0] + red[1] + red[2] + red[3] + red[4] + red[5] + red[6] + red[7];
    float sc = 1.f / (sqrtf(tot) + 1e-12f);
    float v[4] = {x.x * sc, x.y * sc, x.z * sc, x.w * sc};
    uint32_t hh[2], ll[2];
#pragma unroll
    for (int j = 0; j < 2; j++) {
        __nv_bfloat16 h0 = __float2bfloat16(v[2 * j]);
        __nv_bfloat16 h1 = __float2bfloat16(v[2 * j + 1]);
        __nv_bfloat16 l0 = __float2bfloat16(v[2 * j] - __bfloat162float(h0));
        __nv_bfloat16 l1 = __float2bfloat16(v[2 * j + 1] - __bfloat162float(h1));
        hh[j] = (uint32_t)__bfloat16_as_ushort(h0) | ((uint32_t)__bfloat16_as_ushort(h1) << 16);
        ll[j] = (uint32_t)__bfloat16_as_ushort(l0) | ((uint32_t)__bfloat16_as_ushort(l1) << 16);
    }
    ((uint2*)(g_neh + (size_t)r * DIM))[tid] = make_uint2(hh[0], hh[1]);
    ((uint2*)(g_nel + (size_t)r * DIM))[tid] = make_uint2(ll[0], ll[1]);
}

// ==================== K2: A = clamp(ne @ ne^T), HMMA split-3, single-buffer, 2 CTA/SM ====================
#define AKC 64
#define ACH (DIM / AKC)
#define A_AH 0
#define A_AL 16384
#define A_BH 32768
#define A_BL 49152
#define A_DSMEM (1024 + 128 * 130 * 4)

__global__ void __launch_bounds__(256, 2) k_gemmA_mma() {
    extern __shared__ char dsm[];
    __shared__ float sred[8];
    uint32_t raw = smem_u32(dsm);
    uint32_t sbase = ((raw + 1023u) & ~1023u);
    char* sgen = dsm + (sbase - raw);
    uint32_t stg = sbase;

    int tid = threadIdx.x, wid = tid >> 5, lane = tid & 31;
    int wm = wid >> 2, wn = wid & 3;

    int b = blockIdx.x;
    int ti = 0;
    while ((ti + 1) * GT - ti * (ti + 1) / 2 <= b) ti++;
    int tj = ti + (b - (ti * GT - ti * (ti - 1) / 2));
    int r0 = ti * 128, c0 = tj * 128;

    auto load_stage = [&](int k0) {
        int g = tid & 7, rb = tid >> 3;
#pragma unroll
        for (int j = 0; j < 4; j++) {
            int row = rb + 32 * j;
            size_t ga = (size_t)(r0 + row) * DIM + k0 + g * 8;
            size_t gb = (size_t)(c0 + row) * DIM + k0 + g * 8;
            uint32_t so = swz(row, g);
            cp16(stg + A_AH + so, g_neh + ga);
            cp16(stg + A_AL + so, g_nel + ga);
            cp16(stg + A_BH + so, g_neh + gb);
            cp16(stg + A_BL + so, g_nel + gb);
        }
        cp_commit();
    };

    float acc[4][4][4];
#pragma unroll
    for (int q = 0; q < 4; q++)
#pragma unroll
        for (int nt = 0; nt < 4; nt++)
#pragma unroll
            for (int e = 0; e < 4; e++) acc[q][nt][e] = 0.f;

    load_stage(0);

    for (int c = 0; c < ACH; c++) {
        cp_wait<0>();
        __syncthreads();
#pragma unroll
        for (int ks = 0; ks < 4; ks++) {
            uint32_t ah[4][4], al[4][4];
#pragma unroll
            for (int q = 0; q < 4; q++) {
                uint32_t off = swz(wm * 64 + q * 16 + (lane & 15), ks * 2 + (lane >> 4));
                ldmx4(ah[q], stg + A_AH + off);
                ldmx4(al[q], stg + A_AL + off);
            }
            uint32_t bh[4][2], bl[4][2];
#pragma unroll
            for (int p = 0; p < 2; p++) {
                uint32_t row = wn * 32 + p * 16 + (lane & 7) + ((lane >> 4) & 1) * 8;
                uint32_t off = swz(row, ks * 2 + ((lane >> 3) & 1));
                uint32_t t4[4];
                ldmx4(t4, stg + A_BH + off);
                bh[2 * p][0] = t4[0]; bh[2 * p][1] = t4[1];
                bh[2 * p + 1][0] = t4[2]; bh[2 * p + 1][1] = t4[3];
                ldmx4(t4, stg + A_BL + off);
                bl[2 * p][0] = t4[0]; bl[2 * p][1] = t4[1];
                bl[2 * p + 1][0] = t4[2]; bl[2 * p + 1][1] = t4[3];
            }
#pragma unroll
            for (int q = 0; q < 4; q++)
#pragma unroll
                for (int nt = 0; nt < 4; nt++) {
                    mma16816_bf(acc[q][nt], ah[q], bh[nt]);
                    mma16816_bf(acc[q][nt], ah[q], bl[nt]);
                    mma16816_bf(acc[q][nt], al[q], bh[nt]);
                }
        }
        __syncthreads();
        if (c + 1 < ACH) load_stage((c + 1) * AKC);
    }

    float* Cs = (float*)sgen;
#pragma unroll
    for (int q = 0; q < 4; q++) {
        int row = wm * 64 + q * 16 + (lane >> 2);
        int col = wn * 32 + (lane & 3) * 2;
#pragma unroll
        for (int nt = 0; nt < 4; nt++) {
            Cs[row * 130 + col + nt * 8]           = acc[q][nt][0];
            Cs[row * 130 + col + nt * 8 + 1]       = acc[q][nt][1];
            Cs[(row + 8) * 130 + col + nt * 8]     = acc[q][nt][2];
            Cs[(row + 8) * 130 + col + nt * 8 + 1] = acc[q][nt][3];
        }
    }
    __syncthreads();
    float s = 0.f;
    for (int idx = tid; idx < 128 * 128; idx += 256) {
        int i = idx >> 7, j = idx & 127;
        int gi = r0 + i, gj = c0 + j;
        float v = Cs[i * 130 + j];
        v = (gi == gj) ? 0.f : fminf(fmaxf(v, 0.f), 1.f);
        s += v;
        g_A[(size_t)gi * BSZ + gj] = v;
    }
    if (ti != tj) {
        for (int idx = tid; idx < 128 * 128; idx += 256) {
            int i = idx >> 7, j = idx & 127;
            float v = Cs[j * 130 + i];
            v = fminf(fmaxf(v, 0.f), 1.f);
            g_A[(size_t)(c0 + i) * BSZ + (r0 + j)] = v;
        }
    }
#pragma unroll
    for (int o = 16; o; o >>= 1) s += __shfl_xor_sync(0xffffffffu, s, o);
    if (lane == 0) sred[wid] = s;
    __syncthreads();
    if (tid == 0) {
        float t = 0.f;
#pragma unroll
        for (int i = 0; i < 8; i++) t += sred[i];
        g_part[b] = t * ((ti == tj) ? 1.f : 2.f);
    }
}

// ==================== K4: zero the padding of g_part (528..1023) ====================
__global__ void k_zeropart() {
    int i = threadIdx.x + NTRI;
    if (i < 1024) g_part[i] = 0.f;
}

// ==================== K5: threshold + fp16 cast of A (mean fused, identical tree) ====================
__global__ void k_splitA() {
    __shared__ float red[1024];
    int tid = threadIdx.x;
    // identical pairwise tree as the old k_mean2 (1024-padded) -> bit-identical mean
    red[tid] = g_part[tid];
    red[tid + 256] = g_part[tid + 256];
    red[tid + 512] = g_part[tid + 512];
    red[tid + 768] = g_part[tid + 768];
    __syncthreads();
    for (int o = 512; o; o >>= 1) {
        for (int i = tid; i < o; i += 256) red[i] += red[i + o];
        __syncthreads();
    }
    float m = red[0] * (1.f / ((float)BSZ * (float)BSZ));

    size_t i = ((size_t)blockIdx.x * 256 + threadIdx.x) * 8;
    float4 v0 = *(const float4*)(g_A + i);
    float4 v1 = *(const float4*)(g_A + i + 4);
    float f[8] = {v0.x, v0.y, v0.z, v0.w, v1.x, v1.y, v1.z, v1.w};
    uint32_t hw[4];
#pragma unroll
    for (int j = 0; j < 4; j++) {
        float f0 = (f[2 * j]     < m) ? 0.f : f[2 * j];
        float f1 = (f[2 * j + 1] < m) ? 0.f : f[2 * j + 1];
        __half h0 = __float2half_rn(f0), h1 = __float2half_rn(f1);
        hw[j] = (uint32_t)__half_as_ushort(h0) | ((uint32_t)__half_as_ushort(h1) << 16);
    }
    *(uint4*)(g_Af16 + i) = make_uint4(hw[0], hw[1], hw[2], hw[3]);
}

// ==================== K6: init X ====================
__global__ void k_initX(const int* __restrict__ labels) {
    int r = blockIdx.x, c = threadIdx.x;
    float v;
    if (r < NLAB) v = (c == labels[r]) ? 1.f : 0.f;
    else          v = (c < NC) ? 0.01f : 0.f;
    g_Xf[0][(size_t)r * NCP + c] = v;
    g_Xt16[0][(size_t)c * BSZ + r] = __float2half_rn(v);
}

// ==================== K7: iteration GEMM (fp16, K-split x4, 3-stage pipeline) ====================
#define I_A 0
#define I_X 16384
#define I_STAGE 32768
#define I_NSTG 3
#define I_DSMEM (1024 + I_NSTG * I_STAGE)

__global__ void __launch_bounds__(256, 2) k_iter_gemm(int t) {
    extern __shared__ char dsm[];
    uint32_t raw = smem_u32(dsm);
    uint32_t sbase = ((raw + 1023u) & ~1023u);
    uint32_t stg = sbase;

    int tid = threadIdx.x, wid = tid >> 5, lane = tid & 31;
    int wm = wid >> 2, wn = wid & 3;
    int ks = blockIdx.x >> 5, mt = blockIdx.x & 31;
    int r0 = mt * 128;
    int kb = ks * (BSZ / NSPL);

    const __half* __restrict__ Af = g_Af16;
    const __half* __restrict__ Xt = g_Xt16[t & 1];

    auto load_stage = [&](int k0, int buf) {
        uint32_t bu = stg + buf * I_STAGE;
        int g = tid & 7, rb = tid >> 3;
#pragma unroll
        for (int j = 0; j < 4; j++) {
            int row = rb + 32 * j;
            size_t ga = (size_t)(r0 + row) * BSZ + kb + k0 + g * 8;
            size_t gx = (size_t)row * BSZ + kb + k0 + g * 8;
            uint32_t so = swz(row, g);
            cp16(bu + I_A + so, Af + ga);
            cp16(bu + I_X + so, Xt + gx);
        }
        cp_commit();
    };

    float acc[4][4][4];
#pragma unroll
    for (int q = 0; q < 4; q++)
#pragma unroll
        for (int nt = 0; nt < 4; nt++)
#pragma unroll
            for (int e = 0; e < 4; e++) acc[q][nt][e] = 0.f;

    const int KCH = (BSZ / NSPL) / AKC;        // 16 chunks
    load_stage(0, 0);
    load_stage(AKC, 1);
    load_stage(2 * AKC, 2);

    for (int c = 0; c < KCH; c++) {
        if (c >= KCH - 1)      cp_wait<0>();
        else if (c == KCH - 2) cp_wait<1>();
        else                   cp_wait<2>();
        __syncthreads();
        uint32_t bu = stg + (c % I_NSTG) * I_STAGE;
#pragma unroll
        for (int kq = 0; kq < 4; kq++) {
            uint32_t a[4][4];
#pragma unroll
            for (int q = 0; q < 4; q++) {
                uint32_t off = swz(wm * 64 + q * 16 + (lane & 15), kq * 2 + (lane >> 4));
                ldmx4(a[q], bu + I_A + off);
            }
            uint32_t bm[4][2];
#pragma unroll
            for (int p = 0; p < 2; p++) {
                uint32_t row = wn * 32 + p * 16 + (lane & 7) + ((lane >> 4) & 1) * 8;
                uint32_t off = swz(row, kq * 2 + ((lane >> 3) & 1));
                uint32_t t4[4];
                ldmx4(t4, bu + I_X + off);
                bm[2 * p][0] = t4[0]; bm[2 * p][1] = t4[1];
                bm[2 * p + 1][0] = t4[2]; bm[2 * p + 1][1] = t4[3];
            }
#pragma unroll
            for (int q = 0; q < 4; q++)
#pragma unroll
                for (int nt = 0; nt < 4; nt++)
                    mma16816_hf(acc[q][nt], a[q], bm[nt]);
        }
        __syncthreads();
        if (c + 3 < KCH) load_stage((c + 3) * AKC, (c + 3) % I_NSTG);
    }

    float* P = g_D[ks];
#pragma unroll
    for (int q = 0; q < 4; q++) {
        int row = wm * 64 + q * 16 + (lane >> 2);
        int col = wn * 32 + 2 * (lane & 3);
#pragma unroll
        for (int nt = 0; nt < 4; nt++) {
            *(float2*)(P + (size_t)(r0 + row) * NCP + col + nt * 8) =
                make_float2(acc[q][nt][0], acc[q][nt][1]);
            *(float2*)(P + (size_t)(r0 + row + 8) * NCP + col + nt * 8) =
                make_float2(acc[q][nt][2], acc[q][nt][3]);
        }
    }
}

// ==================== K8: epilogue (sum partials, div/entropy, staged outputs) ====================
__global__ void __launch_bounds__(256) k_epi(int t) {
    __shared__ __half sp16[NCP * 32];
    int tid = threadIdx.x;
    int row = tid >> 3, part = tid & 7;
    int r0 = blockIdx.x * 32;
    int gr = r0 + row;
    const float* __restrict__ Xin = g_Xf[t & 1];
    float* __restrict__ Xout = g_Xf[(t + 1) & 1];
    float* __restrict__ sXs  = g_sXs + (size_t)t * BSZ * NC;
    float* __restrict__ sEnt = g_sEnt + (size_t)t * BSZ;

    float dd[16], xv[16], num[16];
    float s = 0.f;
    size_t base = (size_t)gr * NCP + part * 16;
#pragma unroll
    for (int v = 0; v < 4; v++) {
        size_t off = base + v * 4;
        float4 acc4 = *(const float4*)(g_D[0] + off);
#pragma unroll
        for (int p = 1; p < NSPL; p++) {
            float4 pp = *(const float4*)(g_D[p] + off);
            acc4.x += pp.x; acc4.y += pp.y; acc4.z += pp.z; acc4.w += pp.w;
        }
        dd[v * 4 + 0] = acc4.x; dd[v * 4 + 1] = acc4.y;
        dd[v * 4 + 2] = acc4.z; dd[v * 4 + 3] = acc4.w;
        float4 x4 = *(const float4*)(Xin + off);
        xv[v * 4 + 0] = x4.x; xv[v * 4 + 1] = x4.y;
        xv[v * 4 + 2] = x4.z; xv[v * 4 + 3] = x4.w;
    }
#pragma unroll
    for (int i = 0; i < 16; i++) {
        int cc = part * 16 + i;
        num[i] = (cc < NC) ? xv[i] * dd[i] : 0.f;
        s += num[i];
    }
    s += __shfl_xor_sync(0xffffffffu, s, 1);
    s += __shfl_xor_sync(0xffffffffu, s, 2);
    s += __shfl_xor_sync(0xffffffffu, s, 4);
    float inv = 1.f / (s + 1e-8f);

    float ep = 0.f;
#pragma unroll
    for (int v = 0; v < 4; v++) {
        float xo4[4];
#pragma unroll
        for (int i = 0; i < 4; i++) {
            int idx = v * 4 + i;
            int cc = part * 16 + idx;
            float dv = num[idx] * inv;
            float xo = xv[idx] + dv;
            if (cc < NC) {
                ep += dv * __logf(dv + 1e-20f);
                sXs[(size_t)gr * NC + cc] = dv;
            }
            xo4[i] = xo;
            sp16[cc * 32 + row] = __float2half_rn(xo);
        }
        *(float4*)(Xout + base + v * 4) = make_float4(xo4[0], xo4[1], xo4[2], xo4[3]);
    }
    ep += __shfl_xor_sync(0xffffffffu, ep, 1);
    ep += __shfl_xor_sync(0xffffffffu, ep, 2);
    ep += __shfl_xor_sync(0xffffffffu, ep, 4);
    if (part == 0) sEnt[gr] = -ep;
    __syncthreads();

    __half* XtN = g_Xt16[(t + 1) & 1];
    for (int idx = tid; idx < NCP * 16; idx += 256) {
        int cc = idx >> 4;
        int pos = (idx & 15) * 2;
        uint32_t h0 = (uint32_t)__half_as_ushort(sp16[cc * 32 + pos]);
        uint32_t h1 = (uint32_t)__half_as_ushort(sp16[cc * 32 + pos + 1]);
        *(uint32_t*)(XtN + (size_t)cc * BSZ + r0 + pos) = h0 | (h1 << 16);
    }
}

// ==================== K9: finalize outputs ====================
__global__ void __launch_bounds__(256) k_finalize(float* __restrict__ outXs,
                                                  float* __restrict__ outEnt) {
    __shared__ float s[NC * NITER];
    int b = blockIdx.x, tid = threadIdx.x;
    for (int i = tid; i < NITER * NC; i += 256) {
        int t = i / NC, cc = i - t * NC;
        s[cc * NITER + t] = g_sXs[((size_t)t * BSZ + b) * NC + cc];
    }
    __syncthreads();
    for (int i = tid; i < NC * NITER; i += 256)
        outXs[(size_t)b * (NC * NITER) + i] = s[i];
    if (tid < NITER)
        outEnt[(size_t)b * NITER + tid] = g_sEnt[(size_t)tid * BSZ + b];
}

// ==================== launch ====================
extern "C" void kernel_launch(void* const* d_in, const int* in_sizes, int n_in,
                              void* d_out, int out_size) {
    (void)in_sizes; (void)n_in; (void)out_size;
    const float* emb = (const float*)d_in[0];
    const int* labels = (const int*)d_in[1];
    float* out = (float*)d_out;
    float* outXs = out;
    float* outEnt = out + (size_t)BSZ * NC * NITER;

    cudaFuncSetAttribute(k_gemmA_mma, cudaFuncAttributeMaxDynamicSharedMemorySize, A_DSMEM);
    cudaFuncSetAttribute(k_iter_gemm, cudaFuncAttributeMaxDynamicSharedMemorySize, I_DSMEM);

    k_normalize<<<BSZ, 256>>>(emb);
    k_zeropart<<<1, 512>>>();
    k_gemmA_mma<<<NTRI, 256, A_DSMEM>>>();
    k_splitA<<<(int)(((size_t)BSZ * BSZ) / (8 * 256)), 256>>>();
    k_initX<<<BSZ, NCP>>>(labels);
    for (int t = 0; t < NITER; t++) {
        k_iter_gemm<<<NSPL * 32, 256, I_DSMEM>>>(t);
        k_epi<<<BSZ / 32, 256>>>(t);
    }
    k_finalize<<<BSZ, 256>>>(outXs, outEnt);
}